// round 6
// baseline (speedup 1.0000x reference)
#include <cuda_runtime.h>
#include <math.h>
#include <stdint.h>

// ---------------- problem constants ----------------
#define BB   64
#define DM   512
#define NH   8
#define DKH  64
#define DI   2048
#define NLAY 4
#define SS   12
#define REP_IDX 1
#define LMAX 385
#define LPAD 392

// ---------------- scratch ----------------
__device__ int   g_seq_len[BB];
__device__ int   g_poi_idx[BB * LMAX];
__device__ int   g_tok_idx[BB * LMAX];
__device__ float g_x [BB * LMAX * DM];
__device__ float g_q [BB * LMAX * DM];
__device__ float g_k [BB * LMAX * DM];
__device__ float g_v [BB * LMAX * DM];
__device__ float g_ao[BB * LMAX * DM];
__device__ float g_y [BB * LMAX * DM];
__device__ float g_h [BB * LMAX * DI];

// ---------------- pack ----------------
__global__ void pack_kernel(const int* __restrict__ npl,
                            const int* __restrict__ ttn, int L) {
    int b = threadIdx.x;
    if (b >= BB) return;
    int start = 0;
    for (int i = 0; i < b; i++) start += npl[i];
    int end = start + npl[b];
    int pos = 1;
    for (int p = start; p < end; p++) {
        int t = ttn[p];
        for (int u = 0; u < t && pos < L; u++) {
            g_poi_idx[b * L + pos] = p;
            g_tok_idx[b * L + pos] = u;
            pos++;
        }
    }
    g_seq_len[b] = pos;
}

// ---------------- block reduce (128 threads) ----------------
__device__ __forceinline__ void block_reduce2_128(float& s, float& sq) {
    #pragma unroll
    for (int o = 16; o > 0; o >>= 1) {
        s  += __shfl_xor_sync(0xFFFFFFFFu, s,  o);
        sq += __shfl_xor_sync(0xFFFFFFFFu, sq, o);
    }
    __shared__ float rs[4], rq[4];
    int w = threadIdx.x >> 5, ln = threadIdx.x & 31;
    if (ln == 0) { rs[w] = s; rq[w] = sq; }
    __syncthreads();
    s  = rs[0] + rs[1] + rs[2] + rs[3];
    sq = rq[0] + rq[1] + rq[2] + rq[3];
}

__device__ __forceinline__ float postab(int t, int d) {
    int i2 = d & ~1;
    float f = powf(10000.0f, -(float)i2 / (float)DM);
    float ang = (float)t * f;
    return (d & 1) ? cosf(ang) : sinf(ang);
}

// ---------------- embed + final LN ----------------
__global__ __launch_bounds__(128) void embed_ln_kernel(
    const int* __restrict__ poi_type, const float* __restrict__ loc_emb,
    const float* __restrict__ emb, const float* __restrict__ lnf_g,
    const float* __restrict__ lnf_b, int L) {
    int row = blockIdx.x;
    int b = row / L, l = row - b * L;
    int tid = threadIdx.x;
    int d0 = tid * 4;
    float v[4];
    int sl = g_seq_len[b];
    if (l == 0) {
        #pragma unroll
        for (int i = 0; i < 4; i++) v[i] = emb[REP_IDX * DM + d0 + i];
    } else if (l < sl) {
        int p = g_poi_idx[b * L + l];
        int t = g_tok_idx[b * L + l];
        int tok = poi_type[p * SS + t];
        #pragma unroll
        for (int i = 0; i < 4; i++) {
            int d = d0 + i;
            v[i] = emb[tok * DM + d] + postab(t, d) + loc_emb[p * DM + d];
        }
    } else {
        #pragma unroll
        for (int i = 0; i < 4; i++) v[i] = 0.0f;
    }
    float s = v[0] + v[1] + v[2] + v[3];
    float sq = v[0]*v[0] + v[1]*v[1] + v[2]*v[2] + v[3]*v[3];
    block_reduce2_128(s, sq);
    float mean = s * (1.0f / DM);
    float var  = sq * (1.0f / DM) - mean * mean;
    float r = rsqrtf(var + 1e-6f);
    float4 o;
    o.x = lnf_g[d0+0] * (v[0]-mean) * r + lnf_b[d0+0];
    o.y = lnf_g[d0+1] * (v[1]-mean) * r + lnf_b[d0+1];
    o.z = lnf_g[d0+2] * (v[2]-mean) * r + lnf_b[d0+2];
    o.w = lnf_g[d0+3] * (v[3]-mean) * r + lnf_b[d0+3];
    *(float4*)(g_x + (size_t)row * DM + d0) = o;
}

// ---------------- residual + LN ----------------
__global__ __launch_bounds__(128) void resid_ln_kernel(
    float* __restrict__ x, const float* __restrict__ y,
    const float* __restrict__ g, const float* __restrict__ bb) {
    size_t base = (size_t)blockIdx.x * DM + threadIdx.x * 4;
    float4 xv = *(float4*)(x + base);
    float4 yv = *(const float4*)(y + base);
    float v[4] = { xv.x + yv.x, xv.y + yv.y, xv.z + yv.z, xv.w + yv.w };
    float s = v[0] + v[1] + v[2] + v[3];
    float sq = v[0]*v[0] + v[1]*v[1] + v[2]*v[2] + v[3]*v[3];
    block_reduce2_128(s, sq);
    float mean = s * (1.0f / DM);
    float var  = sq * (1.0f / DM) - mean * mean;
    float r = rsqrtf(var + 1e-6f);
    int d0 = threadIdx.x * 4;
    float4 o;
    o.x = g[d0+0] * (v[0]-mean) * r + bb[d0+0];
    o.y = g[d0+1] * (v[1]-mean) * r + bb[d0+1];
    o.z = g[d0+2] * (v[2]-mean) * r + bb[d0+2];
    o.w = g[d0+3] * (v[3]-mean) * r + bb[d0+3];
    *(float4*)(x + base) = o;
}

// ---------------- tf32 helpers ----------------
__device__ __forceinline__ float f2tf(float x) {
    uint32_t u;
    asm("cvt.rna.tf32.f32 %0, %1;" : "=r"(u) : "f"(x));
    return __uint_as_float(u);
}
__device__ __forceinline__ float4 f2tf4(float4 a) {
    return make_float4(f2tf(a.x), f2tf(a.y), f2tf(a.z), f2tf(a.w));
}

__device__ __forceinline__ void mma1688(float* c, const uint32_t* a, const uint32_t* b) {
    asm volatile(
        "mma.sync.aligned.m16n8k8.row.col.f32.tf32.tf32.f32 "
        "{%0,%1,%2,%3}, {%4,%5,%6,%7}, {%8,%9}, {%0,%1,%2,%3};"
        : "+f"(c[0]), "+f"(c[1]), "+f"(c[2]), "+f"(c[3])
        : "r"(a[0]), "r"(a[1]), "r"(a[2]), "r"(a[3]),
          "r"(b[0]), "r"(b[1]));
}

// ---------------- tf32 tensor-core GEMM core ----------------
// 64x128 block tile, 128 threads (4 warps along N, warp tile 64x32),
// BK=16 double-buffered. Target 4 CTAs/SM for latency hiding.
#define AST 72
#define BST 136
__device__ __forceinline__ void gemm_core(
    const float* __restrict__ A, const float* __restrict__ W,
    const float* __restrict__ bias, float* __restrict__ C,
    int M, int N, int K, int do_relu, int row0, int col0) {
    __shared__ float As[2][16][AST];
    __shared__ float Bs[2][16][BST];
    const int tid = threadIdx.x;
    const int wid = tid >> 5, lane = tid & 31;
    const int wn  = wid * 32;

    const int a_row = tid >> 1, a_k = (tid & 1) * 8;
    const int b_k   = tid >> 5, b_n = (tid & 31) * 4;

    float acc[4][4][4];
    #pragma unroll
    for (int mt = 0; mt < 4; mt++)
        #pragma unroll
        for (int nt = 0; nt < 4; nt++)
            #pragma unroll
            for (int i = 0; i < 4; i++) acc[mt][nt][i] = 0.0f;

    float4 sa0, sa1, sb[4];

    auto gload = [&](int k0) {
        int gr = row0 + a_row;
        if (gr < M) {
            const float* ap = A + (size_t)gr * K + k0 + a_k;
            sa0 = *(const float4*)(ap);
            sa1 = *(const float4*)(ap + 4);
        } else {
            sa0 = make_float4(0.f,0.f,0.f,0.f);
            sa1 = sa0;
        }
        #pragma unroll
        for (int j = 0; j < 4; j++)
            sb[j] = *(const float4*)(W + (size_t)(k0 + b_k + 4*j) * N + col0 + b_n);
    };
    auto sstore = [&](int bf) {
        As[bf][a_k+0][a_row] = f2tf(sa0.x);
        As[bf][a_k+1][a_row] = f2tf(sa0.y);
        As[bf][a_k+2][a_row] = f2tf(sa0.z);
        As[bf][a_k+3][a_row] = f2tf(sa0.w);
        As[bf][a_k+4][a_row] = f2tf(sa1.x);
        As[bf][a_k+5][a_row] = f2tf(sa1.y);
        As[bf][a_k+6][a_row] = f2tf(sa1.z);
        As[bf][a_k+7][a_row] = f2tf(sa1.w);
        #pragma unroll
        for (int j = 0; j < 4; j++)
            *(float4*)&Bs[bf][b_k + 4*j][b_n] = f2tf4(sb[j]);
    };

    gload(0);
    sstore(0);
    __syncthreads();

    const int r = lane >> 2, c = lane & 3;
    int buf = 0;
    for (int k0 = 0; k0 < K; k0 += 16) {
        bool nxt = (k0 + 16) < K;
        if (nxt) gload(k0 + 16);
        #pragma unroll
        for (int ks = 0; ks < 16; ks += 8) {
            uint32_t af[4][4], bfr[4][2];
            #pragma unroll
            for (int mt = 0; mt < 4; mt++) {
                int mb = mt * 16 + r;
                af[mt][0] = __float_as_uint(As[buf][ks + c    ][mb    ]);
                af[mt][1] = __float_as_uint(As[buf][ks + c    ][mb + 8]);
                af[mt][2] = __float_as_uint(As[buf][ks + c + 4][mb    ]);
                af[mt][3] = __float_as_uint(As[buf][ks + c + 4][mb + 8]);
            }
            #pragma unroll
            for (int nt = 0; nt < 4; nt++) {
                int nb = wn + nt * 8 + r;
                bfr[nt][0] = __float_as_uint(Bs[buf][ks + c    ][nb]);
                bfr[nt][1] = __float_as_uint(Bs[buf][ks + c + 4][nb]);
            }
            #pragma unroll
            for (int mt = 0; mt < 4; mt++)
                #pragma unroll
                for (int nt = 0; nt < 4; nt++)
                    mma1688(acc[mt][nt], af[mt], bfr[nt]);
        }
        if (nxt) sstore(buf ^ 1);
        __syncthreads();
        buf ^= 1;
    }

    #pragma unroll
    for (int mt = 0; mt < 4; mt++) {
        int rrow = row0 + mt * 16 + (lane >> 2);
        #pragma unroll
        for (int nt = 0; nt < 4; nt++) {
            int ccol = col0 + wn + nt * 8 + (lane & 3) * 2;
            float2 v0 = make_float2(acc[mt][nt][0], acc[mt][nt][1]);
            float2 v1 = make_float2(acc[mt][nt][2], acc[mt][nt][3]);
            if (bias) {
                float b0 = bias[ccol], b1 = bias[ccol + 1];
                v0.x += b0; v0.y += b1;
                v1.x += b0; v1.y += b1;
            }
            if (do_relu) {
                v0.x = fmaxf(v0.x, 0.f); v0.y = fmaxf(v0.y, 0.f);
                v1.x = fmaxf(v1.x, 0.f); v1.y = fmaxf(v1.y, 0.f);
            }
            if (rrow < M)     *(float2*)(C + (size_t)rrow     * N + ccol) = v0;
            if (rrow + 8 < M) *(float2*)(C + (size_t)(rrow+8) * N + ccol) = v1;
        }
    }
}

__global__ __launch_bounds__(128, 4) void mma_gemm_kernel(
    const float* __restrict__ A, const float* __restrict__ W,
    const float* __restrict__ bias, float* __restrict__ C,
    int M, int N, int K, int do_relu) {
    gemm_core(A, W, bias, C, M, N, K, do_relu, blockIdx.y * 64, blockIdx.x * 128);
}

// fused Q/K/V projection: blockIdx.z selects the weight/output
__global__ __launch_bounds__(128, 4) void qkv_gemm_kernel(
    const float* __restrict__ X,
    const float* __restrict__ Wq, const float* __restrict__ Wk,
    const float* __restrict__ Wv,
    float* __restrict__ Qo, float* __restrict__ Ko, float* __restrict__ Vo,
    int M) {
    const float* W = (blockIdx.z == 0) ? Wq : ((blockIdx.z == 1) ? Wk : Wv);
    float*       C = (blockIdx.z == 0) ? Qo : ((blockIdx.z == 1) ? Ko : Vo);
    gemm_core(X, W, nullptr, C, M, DM, DM, 0, blockIdx.y * 64, blockIdx.x * 128);
}

// ---------------- attention ----------------
// Block per (b,h). Full K head slice staged once in dynamic smem with a
// 17-chunk row (stride 68 floats; half-1 dims start at chunk 9 = float 36):
// bank-group = (jt + half + d) mod 8 -> optimal 4 wavefronts per LDS.128.
// Each warp processes 2 queries; dims split across lane pairs.
#define KSTRW 68
__global__ __launch_bounds__(256) void attn_kernel(
    const float* __restrict__ Q, const float* __restrict__ K,
    const float* __restrict__ V, float* __restrict__ O, int L) {
    extern __shared__ float kt[];       // [L][KSTRW]
    __shared__ float sc[16][LPAD];
    int b = blockIdx.x, h = blockIdx.y;
    int tid = threadIdx.x;
    int w = tid >> 5, lane = tid & 31;
    int half = lane & 1, jj = lane >> 1;
    int sl = g_seq_len[b];
    size_t base = ((size_t)b * L) * DM + h * DKH;

    // stage K once (chunk cc goes to float offset cc*4, +4 extra for cc>=8)
    for (int idx = tid; idx < L * 16; idx += 256) {
        int rr = idx >> 4, cc = idx & 15;
        float4 kv = *(const float4*)(K + base + (size_t)rr * DM + cc * 4);
        int off = cc * 4 + ((cc >= 8) ? 4 : 0);
        *(float4*)&kt[rr * KSTRW + off] = kv;
    }
    __syncthreads();

    const int ntile = (L + 15) / 16;
    for (int i0 = w * 2; i0 < L; i0 += 16) {
        int i1 = i0 + 1;
        bool has1 = (i1 < L);
        float4 qa[8], qb[8];
        {
            const float4* q0p = (const float4*)(Q + base + (size_t)i0 * DM + half * 32);
            #pragma unroll
            for (int d = 0; d < 8; d++) qa[d] = q0p[d];
            if (has1) {
                const float4* q1p = (const float4*)(Q + base + (size_t)i1 * DM + half * 32);
                #pragma unroll
                for (int d = 0; d < 8; d++) qb[d] = q1p[d];
            } else {
                #pragma unroll
                for (int d = 0; d < 8; d++) qb[d] = make_float4(0.f,0.f,0.f,0.f);
            }
        }
        float mval = -3.0e38f;
        for (int t = 0; t < ntile; t++) {
            int jt = t * 16 + jj;
            bool valid = (jt < sl);
            float d0 = 0.f, d1 = 0.f;
            if (valid) {
                const float* kp = &kt[jt * KSTRW + half * 36];
                #pragma unroll
                for (int d = 0; d < 8; d++) {
                    float4 kv = *(const float4*)(kp + d * 4);
                    d0 += qa[d].x*kv.x + qa[d].y*kv.y + qa[d].z*kv.z + qa[d].w*kv.w;
                    d1 += qb[d].x*kv.x + qb[d].y*kv.y + qb[d].z*kv.z + qb[d].w*kv.w;
                }
            }
            d0 += __shfl_xor_sync(0xFFFFFFFFu, d0, 1);
            d1 += __shfl_xor_sync(0xFFFFFFFFu, d1, 1);
            float s0 = valid ? d0 * 0.125f : -1e9f;
            float s1 = valid ? d1 * 0.125f : -1e9f;
            if (jt < L) {
                if (half == 0) { sc[2*w  ][jt] = s0; mval = fmaxf(mval, s0); }
                else           { sc[2*w+1][jt] = s1; mval = fmaxf(mval, s1); }
            }
        }
        #pragma unroll
        for (int o = 2; o <= 16; o <<= 1)
            mval = fmaxf(mval, __shfl_xor_sync(0xFFFFFFFFu, mval, o));
        float sum = 0.f;
        int myrow = 2 * w + half;
        for (int t = 0; t < ntile; t++) {
            int jt = t * 16 + jj;
            if (jt < L) {
                float e = expf(sc[myrow][jt] - mval);
                sc[myrow][jt] = e;
                sum += e;
            }
        }
        #pragma unroll
        for (int o = 2; o <= 16; o <<= 1)
            sum += __shfl_xor_sync(0xFFFFFFFFu, sum, o);
        float inv = 1.0f / sum;
        float inv0 = __shfl_sync(0xFFFFFFFFu, inv, 0);
        float inv1 = __shfl_sync(0xFFFFFFFFu, inv, 1);
        __syncwarp();
        float ax0 = 0.f, ay0 = 0.f, ax1 = 0.f, ay1 = 0.f;
        const float* vp = V + base + 2 * lane;
        #pragma unroll 4
        for (int j = 0; j < L; j++) {
            float2 vv = *(const float2*)(vp + (size_t)j * DM);
            float p0 = sc[2*w  ][j];
            float p1 = sc[2*w+1][j];
            ax0 += p0 * vv.x; ay0 += p0 * vv.y;
            ax1 += p1 * vv.x; ay1 += p1 * vv.y;
        }
        *(float2*)(O + base + (size_t)i0 * DM + 2 * lane) =
            make_float2(ax0 * inv0, ay0 * inv0);
        if (has1)
            *(float2*)(O + base + (size_t)i1 * DM + 2 * lane) =
                make_float2(ax1 * inv1, ay1 * inv1);
        __syncwarp();
    }
}

// ---------------- writeout ----------------
__global__ void writeout_kernel(float* __restrict__ out, int L, int with_mask) {
    int idx = blockIdx.x * blockDim.x + threadIdx.x;
    int total = BB * L * DM;
    if (idx < total) out[idx] = g_x[idx];
    if (with_mask && idx < BB * L) {
        int b = idx / L, l = idx - b * L;
        out[total + idx] = (l < g_seq_len[b]) ? 1.0f : 0.0f;
    }
}

// ---------------- host launcher ----------------
extern "C" void kernel_launch(void* const* d_in, const int* in_sizes, int n_in,
                              void* d_out, int out_size) {
    const int*   poi_type = (const int*)  d_in[0];
    const float* loc_emb  = (const float*)d_in[1];
    const int*   npl      = (const int*)  d_in[2];
    const int*   ttn      = (const int*)  d_in[3];
    const float* emb      = (const float*)d_in[4];
    const float* Wq       = (const float*)d_in[5];
    const float* Wk       = (const float*)d_in[6];
    const float* Wv       = (const float*)d_in[7];
    const float* Wo       = (const float*)d_in[8];
    const float* bo       = (const float*)d_in[9];
    const float* ln1_g    = (const float*)d_in[10];
    const float* ln1_b    = (const float*)d_in[11];
    const float* W1       = (const float*)d_in[12];
    const float* b1       = (const float*)d_in[13];
    const float* W2       = (const float*)d_in[14];
    const float* b2       = (const float*)d_in[15];
    const float* ln2_g    = (const float*)d_in[16];
    const float* ln2_b    = (const float*)d_in[17];
    const float* lnf_g    = (const float*)d_in[18];
    const float* lnf_b    = (const float*)d_in[19];

    int L, with_mask;
    if (out_size % (BB * (DM + 1)) == 0) { L = out_size / (BB * (DM + 1)); with_mask = 1; }
    else                                 { L = out_size / (BB * DM);        with_mask = 0; }
    const int M = BB * L;

    float *x, *q, *k, *v, *ao, *y, *hbuf;
    cudaGetSymbolAddress((void**)&x,    g_x);
    cudaGetSymbolAddress((void**)&q,    g_q);
    cudaGetSymbolAddress((void**)&k,    g_k);
    cudaGetSymbolAddress((void**)&v,    g_v);
    cudaGetSymbolAddress((void**)&ao,   g_ao);
    cudaGetSymbolAddress((void**)&y,    g_y);
    cudaGetSymbolAddress((void**)&hbuf, g_h);

    int attn_smem = L * KSTRW * 4;
    cudaFuncSetAttribute(attn_kernel,
                         cudaFuncAttributeMaxDynamicSharedMemorySize,
                         LMAX * KSTRW * 4);

    pack_kernel<<<1, 64>>>(npl, ttn, L);
    embed_ln_kernel<<<M, 128>>>(poi_type, loc_emb, emb, lnf_g, lnf_b, L);

    int my = (M + 63) / 64;
    dim3 g512(4, my);
    dim3 g2048(16, my);
    dim3 gqkv(4, my, 3);
    dim3 gattn(BB, NH);

    for (int l = 0; l < NLAY; l++) {
        const float* wq = Wq + (size_t)l * DM * DM;
        const float* wk = Wk + (size_t)l * DM * DM;
        const float* wv = Wv + (size_t)l * DM * DM;
        const float* wo = Wo + (size_t)l * DM * DM;
        const float* w1 = W1 + (size_t)l * DM * DI;
        const float* w2 = W2 + (size_t)l * DI * DM;

        qkv_gemm_kernel<<<gqkv, 128>>>(x, wq, wk, wv, q, k, v, M);
        attn_kernel<<<gattn, 256, attn_smem>>>(q, k, v, ao, L);
        mma_gemm_kernel<<<g512, 128>>>(ao, wo, bo + (size_t)l * DM, y, M, DM, DM, 0);
        resid_ln_kernel<<<M, 128>>>(x, y, ln1_g + (size_t)l * DM, ln1_b + (size_t)l * DM);
        mma_gemm_kernel<<<g2048, 128>>>(x, w1, b1 + (size_t)l * DI, hbuf, M, DI, DM, 1);
        mma_gemm_kernel<<<g512, 128>>>(hbuf, w2, b2 + (size_t)l * DM, y, M, DM, DI, 0);
        resid_ln_kernel<<<M, 128>>>(x, y, ln2_g + (size_t)l * DM, ln2_b + (size_t)l * DM);
    }

    int n_out = BB * L * DM + (with_mask ? BB * L : 0);
    writeout_kernel<<<(n_out + 255) / 256, 256>>>((float*)d_out, L, with_mask);
}

// round 7
// speedup vs baseline: 1.5765x; 1.5765x over previous
#include <cuda_runtime.h>
#include <math.h>
#include <stdint.h>

// ---------------- problem constants ----------------
#define BB   64
#define DM   512
#define NH   8
#define DKH  64
#define DI   2048
#define NLAY 4
#define SS   12
#define REP_IDX 1
#define LMAX 385
#define LPAD 392

// ---------------- scratch ----------------
__device__ int   g_seq_len[BB];
__device__ int   g_poi_idx[BB * LMAX];
__device__ int   g_tok_idx[BB * LMAX];
__device__ float g_x [BB * LMAX * DM];
__device__ float g_q [BB * LMAX * DM];
__device__ float g_k [BB * LMAX * DM];
__device__ float g_v [BB * LMAX * DM];
__device__ float g_ao[BB * LMAX * DM];
__device__ float g_y [BB * LMAX * DM];
__device__ float g_h [BB * LMAX * DI];

// ---------------- pack ----------------
__global__ void pack_kernel(const int* __restrict__ npl,
                            const int* __restrict__ ttn, int L) {
    int b = threadIdx.x;
    if (b >= BB) return;
    int start = 0;
    for (int i = 0; i < b; i++) start += npl[i];
    int end = start + npl[b];
    int pos = 1;
    for (int p = start; p < end; p++) {
        int t = ttn[p];
        for (int u = 0; u < t && pos < L; u++) {
            g_poi_idx[b * L + pos] = p;
            g_tok_idx[b * L + pos] = u;
            pos++;
        }
    }
    g_seq_len[b] = pos;
}

// ---------------- block reduce (128 threads) ----------------
__device__ __forceinline__ void block_reduce2_128(float& s, float& sq) {
    #pragma unroll
    for (int o = 16; o > 0; o >>= 1) {
        s  += __shfl_xor_sync(0xFFFFFFFFu, s,  o);
        sq += __shfl_xor_sync(0xFFFFFFFFu, sq, o);
    }
    __shared__ float rs[4], rq[4];
    int w = threadIdx.x >> 5, ln = threadIdx.x & 31;
    if (ln == 0) { rs[w] = s; rq[w] = sq; }
    __syncthreads();
    s  = rs[0] + rs[1] + rs[2] + rs[3];
    sq = rq[0] + rq[1] + rq[2] + rq[3];
}

__device__ __forceinline__ float postab(int t, int d) {
    int i2 = d & ~1;
    float f = powf(10000.0f, -(float)i2 / (float)DM);
    float ang = (float)t * f;
    return (d & 1) ? cosf(ang) : sinf(ang);
}

// ---------------- embed + final LN ----------------
__global__ __launch_bounds__(128) void embed_ln_kernel(
    const int* __restrict__ poi_type, const float* __restrict__ loc_emb,
    const float* __restrict__ emb, const float* __restrict__ lnf_g,
    const float* __restrict__ lnf_b, int L) {
    int row = blockIdx.x;
    int b = row / L, l = row - b * L;
    int tid = threadIdx.x;
    int d0 = tid * 4;
    float v[4];
    int sl = g_seq_len[b];
    if (l == 0) {
        #pragma unroll
        for (int i = 0; i < 4; i++) v[i] = emb[REP_IDX * DM + d0 + i];
    } else if (l < sl) {
        int p = g_poi_idx[b * L + l];
        int t = g_tok_idx[b * L + l];
        int tok = poi_type[p * SS + t];
        #pragma unroll
        for (int i = 0; i < 4; i++) {
            int d = d0 + i;
            v[i] = emb[tok * DM + d] + postab(t, d) + loc_emb[p * DM + d];
        }
    } else {
        #pragma unroll
        for (int i = 0; i < 4; i++) v[i] = 0.0f;
    }
    float s = v[0] + v[1] + v[2] + v[3];
    float sq = v[0]*v[0] + v[1]*v[1] + v[2]*v[2] + v[3]*v[3];
    block_reduce2_128(s, sq);
    float mean = s * (1.0f / DM);
    float var  = sq * (1.0f / DM) - mean * mean;
    float r = rsqrtf(var + 1e-6f);
    float4 o;
    o.x = lnf_g[d0+0] * (v[0]-mean) * r + lnf_b[d0+0];
    o.y = lnf_g[d0+1] * (v[1]-mean) * r + lnf_b[d0+1];
    o.z = lnf_g[d0+2] * (v[2]-mean) * r + lnf_b[d0+2];
    o.w = lnf_g[d0+3] * (v[3]-mean) * r + lnf_b[d0+3];
    *(float4*)(g_x + (size_t)row * DM + d0) = o;
}

// ---------------- residual + LN ----------------
__global__ __launch_bounds__(128) void resid_ln_kernel(
    float* __restrict__ x, const float* __restrict__ y,
    const float* __restrict__ g, const float* __restrict__ bb) {
    size_t base = (size_t)blockIdx.x * DM + threadIdx.x * 4;
    float4 xv = *(float4*)(x + base);
    float4 yv = *(const float4*)(y + base);
    float v[4] = { xv.x + yv.x, xv.y + yv.y, xv.z + yv.z, xv.w + yv.w };
    float s = v[0] + v[1] + v[2] + v[3];
    float sq = v[0]*v[0] + v[1]*v[1] + v[2]*v[2] + v[3]*v[3];
    block_reduce2_128(s, sq);
    float mean = s * (1.0f / DM);
    float var  = sq * (1.0f / DM) - mean * mean;
    float r = rsqrtf(var + 1e-6f);
    int d0 = threadIdx.x * 4;
    float4 o;
    o.x = g[d0+0] * (v[0]-mean) * r + bb[d0+0];
    o.y = g[d0+1] * (v[1]-mean) * r + bb[d0+1];
    o.z = g[d0+2] * (v[2]-mean) * r + bb[d0+2];
    o.w = g[d0+3] * (v[3]-mean) * r + bb[d0+3];
    *(float4*)(x + base) = o;
}

// ---------------- tf32 helpers ----------------
__device__ __forceinline__ float f2tf(float x) {
    uint32_t u;
    asm("cvt.rna.tf32.f32 %0, %1;" : "=r"(u) : "f"(x));
    return __uint_as_float(u);
}
__device__ __forceinline__ float4 f2tf4(float4 a) {
    return make_float4(f2tf(a.x), f2tf(a.y), f2tf(a.z), f2tf(a.w));
}

__device__ __forceinline__ void mma1688(float* c, const uint32_t* a, const uint32_t* b) {
    asm volatile(
        "mma.sync.aligned.m16n8k8.row.col.f32.tf32.tf32.f32 "
        "{%0,%1,%2,%3}, {%4,%5,%6,%7}, {%8,%9}, {%0,%1,%2,%3};"
        : "+f"(c[0]), "+f"(c[1]), "+f"(c[2]), "+f"(c[3])
        : "r"(a[0]), "r"(a[1]), "r"(a[2]), "r"(a[3]),
          "r"(b[0]), "r"(b[1]));
}

// ---------------- tf32 tensor-core GEMM core ----------------
#define AST 72
#define BST 136
__device__ __forceinline__ void gemm_core(
    const float* __restrict__ A, const float* __restrict__ W,
    const float* __restrict__ bias, float* __restrict__ C,
    int M, int N, int K, int do_relu, int row0, int col0) {
    __shared__ float As[2][16][AST];
    __shared__ float Bs[2][16][BST];
    const int tid = threadIdx.x;
    const int wid = tid >> 5, lane = tid & 31;
    const int wn  = wid * 32;

    const int a_row = tid >> 1, a_k = (tid & 1) * 8;
    const int b_k   = tid >> 5, b_n = (tid & 31) * 4;

    float acc[4][4][4];
    #pragma unroll
    for (int mt = 0; mt < 4; mt++)
        #pragma unroll
        for (int nt = 0; nt < 4; nt++)
            #pragma unroll
            for (int i = 0; i < 4; i++) acc[mt][nt][i] = 0.0f;

    float4 sa0, sa1, sb[4];

    auto gload = [&](int k0) {
        int gr = row0 + a_row;
        if (gr < M) {
            const float* ap = A + (size_t)gr * K + k0 + a_k;
            sa0 = *(const float4*)(ap);
            sa1 = *(const float4*)(ap + 4);
        } else {
            sa0 = make_float4(0.f,0.f,0.f,0.f);
            sa1 = sa0;
        }
        #pragma unroll
        for (int j = 0; j < 4; j++)
            sb[j] = *(const float4*)(W + (size_t)(k0 + b_k + 4*j) * N + col0 + b_n);
    };
    auto sstore = [&](int bf) {
        As[bf][a_k+0][a_row] = f2tf(sa0.x);
        As[bf][a_k+1][a_row] = f2tf(sa0.y);
        As[bf][a_k+2][a_row] = f2tf(sa0.z);
        As[bf][a_k+3][a_row] = f2tf(sa0.w);
        As[bf][a_k+4][a_row] = f2tf(sa1.x);
        As[bf][a_k+5][a_row] = f2tf(sa1.y);
        As[bf][a_k+6][a_row] = f2tf(sa1.z);
        As[bf][a_k+7][a_row] = f2tf(sa1.w);
        #pragma unroll
        for (int j = 0; j < 4; j++)
            *(float4*)&Bs[bf][b_k + 4*j][b_n] = f2tf4(sb[j]);
    };

    gload(0);
    sstore(0);
    __syncthreads();

    const int r = lane >> 2, c = lane & 3;
    int buf = 0;
    for (int k0 = 0; k0 < K; k0 += 16) {
        bool nxt = (k0 + 16) < K;
        if (nxt) gload(k0 + 16);
        #pragma unroll
        for (int ks = 0; ks < 16; ks += 8) {
            uint32_t af[4][4], bfr[4][2];
            #pragma unroll
            for (int mt = 0; mt < 4; mt++) {
                int mb = mt * 16 + r;
                af[mt][0] = __float_as_uint(As[buf][ks + c    ][mb    ]);
                af[mt][1] = __float_as_uint(As[buf][ks + c    ][mb + 8]);
                af[mt][2] = __float_as_uint(As[buf][ks + c + 4][mb    ]);
                af[mt][3] = __float_as_uint(As[buf][ks + c + 4][mb + 8]);
            }
            #pragma unroll
            for (int nt = 0; nt < 4; nt++) {
                int nb = wn + nt * 8 + r;
                bfr[nt][0] = __float_as_uint(Bs[buf][ks + c    ][nb]);
                bfr[nt][1] = __float_as_uint(Bs[buf][ks + c + 4][nb]);
            }
            #pragma unroll
            for (int mt = 0; mt < 4; mt++)
                #pragma unroll
                for (int nt = 0; nt < 4; nt++)
                    mma1688(acc[mt][nt], af[mt], bfr[nt]);
        }
        if (nxt) sstore(buf ^ 1);
        __syncthreads();
        buf ^= 1;
    }

    #pragma unroll
    for (int mt = 0; mt < 4; mt++) {
        int rrow = row0 + mt * 16 + (lane >> 2);
        #pragma unroll
        for (int nt = 0; nt < 4; nt++) {
            int ccol = col0 + wn + nt * 8 + (lane & 3) * 2;
            float2 v0 = make_float2(acc[mt][nt][0], acc[mt][nt][1]);
            float2 v1 = make_float2(acc[mt][nt][2], acc[mt][nt][3]);
            if (bias) {
                float b0 = bias[ccol], b1 = bias[ccol + 1];
                v0.x += b0; v0.y += b1;
                v1.x += b0; v1.y += b1;
            }
            if (do_relu) {
                v0.x = fmaxf(v0.x, 0.f); v0.y = fmaxf(v0.y, 0.f);
                v1.x = fmaxf(v1.x, 0.f); v1.y = fmaxf(v1.y, 0.f);
            }
            if (rrow < M)     *(float2*)(C + (size_t)rrow     * N + ccol) = v0;
            if (rrow + 8 < M) *(float2*)(C + (size_t)(rrow+8) * N + ccol) = v1;
        }
    }
}

__global__ __launch_bounds__(128, 4) void mma_gemm_kernel(
    const float* __restrict__ A, const float* __restrict__ W,
    const float* __restrict__ bias, float* __restrict__ C,
    int M, int N, int K, int do_relu) {
    gemm_core(A, W, bias, C, M, N, K, do_relu, blockIdx.y * 64, blockIdx.x * 128);
}

__global__ __launch_bounds__(128, 4) void qkv_gemm_kernel(
    const float* __restrict__ X,
    const float* __restrict__ Wq, const float* __restrict__ Wk,
    const float* __restrict__ Wv,
    float* __restrict__ Qo, float* __restrict__ Ko, float* __restrict__ Vo,
    int M) {
    const float* W = (blockIdx.z == 0) ? Wq : ((blockIdx.z == 1) ? Wk : Wv);
    float*       C = (blockIdx.z == 0) ? Qo : ((blockIdx.z == 1) ? Ko : Vo);
    gemm_core(X, W, nullptr, C, M, DM, DM, 0, blockIdx.y * 64, blockIdx.x * 128);
}

// ---------------- MMA attention (flash-style, tf32) ----------------
// Grid (b, h, qtile). 128 threads = 4 warps x 16 queries.
// Per 64-key chunk: S^T = K @ Q^T (K natural row-major in smem; only Q is
// transposed, once per block). Online masked softmax on C-frags (column =
// query -> shfl_xor 4/8/16 reduction). P round-trips through smem (stride 76,
// conflict-free), then O += P @ V with V in natural [key][dim] layout.
#define SKT 76   // sK row stride   (A-frag bank: 12r+c distinct)
#define SVT 72   // sV/sQT stride   (B-frag bank: 8c+r distinct)
#define SPT 76   // sP row stride
// dynamic smem layout (floats):
//   sK : 64*SKT          = 4864
//   sV : 64*SVT          = 4608
//   sQT: 64*SVT          = 4608   [dim][query]
//   sP : 4*16*SPT        = 4864   per-warp [query][key]
//   sW : 4*16             = 64
#define ATTN_SMEM_FLOATS (64*SKT + 64*SVT + 64*SVT + 4*16*SPT + 64)

__global__ __launch_bounds__(128) void attn_mma_kernel(
    const float* __restrict__ Q, const float* __restrict__ K,
    const float* __restrict__ V, float* __restrict__ O, int L) {
    extern __shared__ float sm[];
    float* sK  = sm;                       // [64][SKT]
    float* sV  = sK + 64 * SKT;            // [64][SVT]
    float* sQT = sV + 64 * SVT;            // [64][SVT]  (dim-major)
    float* sPa = sQT + 64 * SVT;           // [4][16][SPT]
    float* sW  = sPa + 4 * 16 * SPT;       // [4][16]

    int b = blockIdx.x, h = blockIdx.y, qt = blockIdx.z;
    int tid = threadIdx.x, w = tid >> 5, lane = tid & 31;
    int r = lane >> 2, c = lane & 3;
    int sl = g_seq_len[b];
    size_t base = ((size_t)b * L) * DM + h * DKH;
    int q0 = qt * 64;
    int qb = w * 16;
    float* sP = sPa + w * 16 * SPT;
    float* sWw = sW + w * 16;

    // stage Q^T once (tf32), queries clamped to L-1 (stores guarded later)
    for (int idx = tid; idx < 64 * 16; idx += 128) {
        int qq = idx >> 4, dd = (idx & 15) * 4;
        int gq = q0 + qq; if (gq >= L) gq = L - 1;
        float4 qv = *(const float4*)(Q + base + (size_t)gq * DM + dd);
        sQT[(dd+0) * SVT + qq] = f2tf(qv.x);
        sQT[(dd+1) * SVT + qq] = f2tf(qv.y);
        sQT[(dd+2) * SVT + qq] = f2tf(qv.z);
        sQT[(dd+3) * SVT + qq] = f2tf(qv.w);
    }

    float oacc[8][4];
    #pragma unroll
    for (int d = 0; d < 8; d++)
        #pragma unroll
        for (int i = 0; i < 4; i++) oacc[d][i] = 0.0f;
    float mrow[2][2] = {{-3.0e38f, -3.0e38f}, {-3.0e38f, -3.0e38f}};
    float lrow[2][2] = {{0.f, 0.f}, {0.f, 0.f}};

    for (int j0 = 0; j0 < L; j0 += 64) {
        __syncthreads();   // previous chunk fully consumed
        // stage K, V chunk (tf32)
        for (int idx = tid; idx < 64 * 16; idx += 128) {
            int kr = idx >> 4, dd = (idx & 15) * 4;
            int gj = j0 + kr;
            float4 kv = make_float4(0.f,0.f,0.f,0.f), vv = kv;
            if (gj < L) {
                kv = *(const float4*)(K + base + (size_t)gj * DM + dd);
                vv = *(const float4*)(V + base + (size_t)gj * DM + dd);
            }
            *(float4*)&sK[kr * SKT + dd] = f2tf4(kv);
            *(float4*)&sV[kr * SVT + dd] = f2tf4(vv);
        }
        __syncthreads();

        // S^T = K @ Q^T  : rows = keys (4 m-tiles), cols = queries (2 n-tiles)
        float sfr[4][2][4];
        #pragma unroll
        for (int mt = 0; mt < 4; mt++)
            #pragma unroll
            for (int nt = 0; nt < 2; nt++)
                #pragma unroll
                for (int i = 0; i < 4; i++) sfr[mt][nt][i] = 0.f;

        #pragma unroll
        for (int kk = 0; kk < 64; kk += 8) {
            uint32_t bq[2][2];
            #pragma unroll
            for (int nt = 0; nt < 2; nt++) {
                int qn = qb + nt * 8 + r;
                bq[nt][0] = __float_as_uint(sQT[(kk + c    ) * SVT + qn]);
                bq[nt][1] = __float_as_uint(sQT[(kk + c + 4) * SVT + qn]);
            }
            #pragma unroll
            for (int mt = 0; mt < 4; mt++) {
                int mb = mt * 16;
                uint32_t a[4];
                a[0] = __float_as_uint(sK[(mb + r    ) * SKT + kk + c    ]);
                a[1] = __float_as_uint(sK[(mb + r + 8) * SKT + kk + c    ]);
                a[2] = __float_as_uint(sK[(mb + r    ) * SKT + kk + c + 4]);
                a[3] = __float_as_uint(sK[(mb + r + 8) * SKT + kk + c + 4]);
                #pragma unroll
                for (int nt = 0; nt < 2; nt++)
                    mma1688(sfr[mt][nt], a, bq[nt]);
            }
        }

        // online masked softmax per query column
        float scl[2][2];
        #pragma unroll
        for (int nt = 0; nt < 2; nt++) {
            #pragma unroll
            for (int i = 0; i < 2; i++) {
                float cm = -3.0e38f;
                #pragma unroll
                for (int mt = 0; mt < 4; mt++) {
                    int j = j0 + mt * 16 + r;
                    float s0 = (j     < sl) ? sfr[mt][nt][i]   * 0.125f : -1e9f;
                    float s1 = (j + 8 < sl) ? sfr[mt][nt][2+i] * 0.125f : -1e9f;
                    sfr[mt][nt][i]   = s0;
                    sfr[mt][nt][2+i] = s1;
                    cm = fmaxf(cm, fmaxf(s0, s1));
                }
                cm = fmaxf(cm, __shfl_xor_sync(0xFFFFFFFFu, cm, 4));
                cm = fmaxf(cm, __shfl_xor_sync(0xFFFFFFFFu, cm, 8));
                cm = fmaxf(cm, __shfl_xor_sync(0xFFFFFFFFu, cm, 16));
                float mnew = fmaxf(mrow[nt][i], cm);
                float sc = expf(mrow[nt][i] - mnew);
                mrow[nt][i] = mnew;
                scl[nt][i] = sc;
                float ls = 0.f;
                #pragma unroll
                for (int mt = 0; mt < 4; mt++) {
                    float p0 = expf(sfr[mt][nt][i]   - mnew);
                    float p1 = expf(sfr[mt][nt][2+i] - mnew);
                    sfr[mt][nt][i]   = p0;
                    sfr[mt][nt][2+i] = p1;
                    ls += p0 + p1;
                }
                ls += __shfl_xor_sync(0xFFFFFFFFu, ls, 4);
                ls += __shfl_xor_sync(0xFFFFFFFFu, ls, 8);
                ls += __shfl_xor_sync(0xFFFFFFFFu, ls, 16);
                lrow[nt][i] = lrow[nt][i] * sc + ls;
            }
        }
        // broadcast per-query rescale to row-indexed lanes
        if (r == 0) {
            #pragma unroll
            for (int nt = 0; nt < 2; nt++)
                #pragma unroll
                for (int i = 0; i < 2; i++)
                    sWw[nt * 8 + 2 * c + i] = scl[nt][i];
        }
        __syncwarp();
        float rs0 = sWw[r], rs1 = sWw[r + 8];
        #pragma unroll
        for (int d = 0; d < 8; d++) {
            oacc[d][0] *= rs0; oacc[d][1] *= rs0;
            oacc[d][2] *= rs1; oacc[d][3] *= rs1;
        }
        // store P^T -> sP[query][key] (tf32)
        #pragma unroll
        for (int nt = 0; nt < 2; nt++)
            #pragma unroll
            for (int i = 0; i < 2; i++) {
                int qq = nt * 8 + 2 * c + i;
                #pragma unroll
                for (int mt = 0; mt < 4; mt++) {
                    sP[qq * SPT + mt * 16 + r    ] = f2tf(sfr[mt][nt][i]);
                    sP[qq * SPT + mt * 16 + r + 8] = f2tf(sfr[mt][nt][2+i]);
                }
            }
        __syncwarp();
        // O += P @ V
        #pragma unroll
        for (int kk = 0; kk < 64; kk += 8) {
            uint32_t a[4];
            a[0] = __float_as_uint(sP[(r    ) * SPT + kk + c    ]);
            a[1] = __float_as_uint(sP[(r + 8) * SPT + kk + c    ]);
            a[2] = __float_as_uint(sP[(r    ) * SPT + kk + c + 4]);
            a[3] = __float_as_uint(sP[(r + 8) * SPT + kk + c + 4]);
            #pragma unroll
            for (int dn = 0; dn < 8; dn++) {
                uint32_t bb2[2];
                bb2[0] = __float_as_uint(sV[(kk + c    ) * SVT + dn * 8 + r]);
                bb2[1] = __float_as_uint(sV[(kk + c + 4) * SVT + dn * 8 + r]);
                mma1688(oacc[dn], a, bb2);
            }
        }
    }

    // normalize + write out
    if (r == 0) {
        #pragma unroll
        for (int nt = 0; nt < 2; nt++)
            #pragma unroll
            for (int i = 0; i < 2; i++)
                sWw[nt * 8 + 2 * c + i] = 1.0f / lrow[nt][i];
    }
    __syncwarp();
    float inv0 = sWw[r], inv1 = sWw[r + 8];
    int gq0 = q0 + qb + r, gq1 = gq0 + 8;
    #pragma unroll
    for (int dn = 0; dn < 8; dn++) {
        int col = dn * 8 + 2 * c;
        if (gq0 < L)
            *(float2*)(O + base + (size_t)gq0 * DM + col) =
                make_float2(oacc[dn][0] * inv0, oacc[dn][1] * inv0);
        if (gq1 < L)
            *(float2*)(O + base + (size_t)gq1 * DM + col) =
                make_float2(oacc[dn][2] * inv1, oacc[dn][3] * inv1);
    }
}

// ---------------- writeout ----------------
__global__ void writeout_kernel(float* __restrict__ out, int L, int with_mask) {
    int idx = blockIdx.x * blockDim.x + threadIdx.x;
    int total = BB * L * DM;
    if (idx < total) out[idx] = g_x[idx];
    if (with_mask && idx < BB * L) {
        int b = idx / L, l = idx - b * L;
        out[total + idx] = (l < g_seq_len[b]) ? 1.0f : 0.0f;
    }
}

// ---------------- host launcher ----------------
extern "C" void kernel_launch(void* const* d_in, const int* in_sizes, int n_in,
                              void* d_out, int out_size) {
    const int*   poi_type = (const int*)  d_in[0];
    const float* loc_emb  = (const float*)d_in[1];
    const int*   npl      = (const int*)  d_in[2];
    const int*   ttn      = (const int*)  d_in[3];
    const float* emb      = (const float*)d_in[4];
    const float* Wq       = (const float*)d_in[5];
    const float* Wk       = (const float*)d_in[6];
    const float* Wv       = (const float*)d_in[7];
    const float* Wo       = (const float*)d_in[8];
    const float* bo       = (const float*)d_in[9];
    const float* ln1_g    = (const float*)d_in[10];
    const float* ln1_b    = (const float*)d_in[11];
    const float* W1       = (const float*)d_in[12];
    const float* b1       = (const float*)d_in[13];
    const float* W2       = (const float*)d_in[14];
    const float* b2       = (const float*)d_in[15];
    const float* ln2_g    = (const float*)d_in[16];
    const float* ln2_b    = (const float*)d_in[17];
    const float* lnf_g    = (const float*)d_in[18];
    const float* lnf_b    = (const float*)d_in[19];

    int L, with_mask;
    if (out_size % (BB * (DM + 1)) == 0) { L = out_size / (BB * (DM + 1)); with_mask = 1; }
    else                                 { L = out_size / (BB * DM);        with_mask = 0; }
    const int M = BB * L;

    float *x, *q, *k, *v, *ao, *y, *hbuf;
    cudaGetSymbolAddress((void**)&x,    g_x);
    cudaGetSymbolAddress((void**)&q,    g_q);
    cudaGetSymbolAddress((void**)&k,    g_k);
    cudaGetSymbolAddress((void**)&v,    g_v);
    cudaGetSymbolAddress((void**)&ao,   g_ao);
    cudaGetSymbolAddress((void**)&y,    g_y);
    cudaGetSymbolAddress((void**)&hbuf, g_h);

    int attn_smem = ATTN_SMEM_FLOATS * 4;
    cudaFuncSetAttribute(attn_mma_kernel,
                         cudaFuncAttributeMaxDynamicSharedMemorySize,
                         attn_smem);

    pack_kernel<<<1, 64>>>(npl, ttn, L);
    embed_ln_kernel<<<M, 128>>>(poi_type, loc_emb, emb, lnf_g, lnf_b, L);

    int my = (M + 63) / 64;
    int nq = (L + 63) / 64;
    dim3 g512(4, my);
    dim3 g2048(16, my);
    dim3 gqkv(4, my, 3);
    dim3 gattn(BB, NH, nq);

    for (int l = 0; l < NLAY; l++) {
        const float* wq = Wq + (size_t)l * DM * DM;
        const float* wk = Wk + (size_t)l * DM * DM;
        const float* wv = Wv + (size_t)l * DM * DM;
        const float* wo = Wo + (size_t)l * DM * DM;
        const float* w1 = W1 + (size_t)l * DM * DI;
        const float* w2 = W2 + (size_t)l * DI * DM;

        qkv_gemm_kernel<<<gqkv, 128>>>(x, wq, wk, wv, q, k, v, M);
        attn_mma_kernel<<<gattn, 128, attn_smem>>>(q, k, v, ao, L);
        mma_gemm_kernel<<<g512, 128>>>(ao, wo, bo + (size_t)l * DM, y, M, DM, DM, 0);
        resid_ln_kernel<<<M, 128>>>(x, y, ln1_g + (size_t)l * DM, ln1_b + (size_t)l * DM);
        mma_gemm_kernel<<<g2048, 128>>>(x, w1, b1 + (size_t)l * DI, hbuf, M, DI, DM, 1);
        mma_gemm_kernel<<<g512, 128>>>(hbuf, w2, b2 + (size_t)l * DM, y, M, DM, DI, 0);
        resid_ln_kernel<<<M, 128>>>(x, y, ln2_g + (size_t)l * DM, ln2_b + (size_t)l * DM);
    }

    int n_out = BB * L * DM + (with_mask ? BB * L : 0);
    writeout_kernel<<<(n_out + 255) / 256, 256>>>((float*)d_out, L, with_mask);
}

// round 8
// speedup vs baseline: 1.9692x; 1.2491x over previous
#include <cuda_runtime.h>
#include <math.h>
#include <stdint.h>

// ---------------- problem constants ----------------
#define BB   64
#define DM   512
#define NH   8
#define DKH  64
#define DI   2048
#define NLAY 4
#define SS   12
#define REP_IDX 1
#define LMAX 385
#define LPAD 392

// ---------------- scratch ----------------
__device__ int   g_seq_len[BB];
__device__ int   g_poi_idx[BB * LMAX];
__device__ int   g_tok_idx[BB * LMAX];
__device__ float g_x [BB * LMAX * DM];
__device__ float g_q [BB * LMAX * DM];
__device__ float g_k [BB * LMAX * DM];
__device__ float g_v [BB * LMAX * DM];
__device__ float g_ao[BB * LMAX * DM];
__device__ float g_y [BB * LMAX * DM];
__device__ float g_h [BB * LMAX * DI];

// ---------------- pack ----------------
__global__ void pack_kernel(const int* __restrict__ npl,
                            const int* __restrict__ ttn, int L) {
    int b = threadIdx.x;
    if (b >= BB) return;
    int start = 0;
    for (int i = 0; i < b; i++) start += npl[i];
    int end = start + npl[b];
    int pos = 1;
    for (int p = start; p < end; p++) {
        int t = ttn[p];
        for (int u = 0; u < t && pos < L; u++) {
            g_poi_idx[b * L + pos] = p;
            g_tok_idx[b * L + pos] = u;
            pos++;
        }
    }
    g_seq_len[b] = pos;
}

// ---------------- block reduce (128 threads) ----------------
__device__ __forceinline__ void block_reduce2_128(float& s, float& sq) {
    #pragma unroll
    for (int o = 16; o > 0; o >>= 1) {
        s  += __shfl_xor_sync(0xFFFFFFFFu, s,  o);
        sq += __shfl_xor_sync(0xFFFFFFFFu, sq, o);
    }
    __shared__ float rs[4], rq[4];
    int w = threadIdx.x >> 5, ln = threadIdx.x & 31;
    if (ln == 0) { rs[w] = s; rq[w] = sq; }
    __syncthreads();
    s  = rs[0] + rs[1] + rs[2] + rs[3];
    sq = rq[0] + rq[1] + rq[2] + rq[3];
}

__device__ __forceinline__ float postab(int t, int d) {
    int i2 = d & ~1;
    float f = powf(10000.0f, -(float)i2 / (float)DM);
    float ang = (float)t * f;
    return (d & 1) ? cosf(ang) : sinf(ang);
}

// ---------------- embed + final LN ----------------
__global__ __launch_bounds__(128) void embed_ln_kernel(
    const int* __restrict__ poi_type, const float* __restrict__ loc_emb,
    const float* __restrict__ emb, const float* __restrict__ lnf_g,
    const float* __restrict__ lnf_b, int L) {
    int row = blockIdx.x;
    int b = row / L, l = row - b * L;
    int tid = threadIdx.x;
    int d0 = tid * 4;
    float v[4];
    int sl = g_seq_len[b];
    if (l == 0) {
        #pragma unroll
        for (int i = 0; i < 4; i++) v[i] = emb[REP_IDX * DM + d0 + i];
    } else if (l < sl) {
        int p = g_poi_idx[b * L + l];
        int t = g_tok_idx[b * L + l];
        int tok = poi_type[p * SS + t];
        #pragma unroll
        for (int i = 0; i < 4; i++) {
            int d = d0 + i;
            v[i] = emb[tok * DM + d] + postab(t, d) + loc_emb[p * DM + d];
        }
    } else {
        #pragma unroll
        for (int i = 0; i < 4; i++) v[i] = 0.0f;
    }
    float s = v[0] + v[1] + v[2] + v[3];
    float sq = v[0]*v[0] + v[1]*v[1] + v[2]*v[2] + v[3]*v[3];
    block_reduce2_128(s, sq);
    float mean = s * (1.0f / DM);
    float var  = sq * (1.0f / DM) - mean * mean;
    float r = rsqrtf(var + 1e-6f);
    float4 o;
    o.x = lnf_g[d0+0] * (v[0]-mean) * r + lnf_b[d0+0];
    o.y = lnf_g[d0+1] * (v[1]-mean) * r + lnf_b[d0+1];
    o.z = lnf_g[d0+2] * (v[2]-mean) * r + lnf_b[d0+2];
    o.w = lnf_g[d0+3] * (v[3]-mean) * r + lnf_b[d0+3];
    *(float4*)(g_x + (size_t)row * DM + d0) = o;
}

// ---------------- residual + LN (dst = LN(x + y); x also updated unless dst==x) ----------------
__global__ __launch_bounds__(128) void resid_ln_kernel(
    float* __restrict__ x, const float* __restrict__ y,
    const float* __restrict__ g, const float* __restrict__ bb,
    float* __restrict__ dst) {
    size_t base = (size_t)blockIdx.x * DM + threadIdx.x * 4;
    float4 xv = *(float4*)(x + base);
    float4 yv = *(const float4*)(y + base);
    float v[4] = { xv.x + yv.x, xv.y + yv.y, xv.z + yv.z, xv.w + yv.w };
    float s = v[0] + v[1] + v[2] + v[3];
    float sq = v[0]*v[0] + v[1]*v[1] + v[2]*v[2] + v[3]*v[3];
    block_reduce2_128(s, sq);
    float mean = s * (1.0f / DM);
    float var  = sq * (1.0f / DM) - mean * mean;
    float r = rsqrtf(var + 1e-6f);
    int d0 = threadIdx.x * 4;
    float4 o;
    o.x = g[d0+0] * (v[0]-mean) * r + bb[d0+0];
    o.y = g[d0+1] * (v[1]-mean) * r + bb[d0+1];
    o.z = g[d0+2] * (v[2]-mean) * r + bb[d0+2];
    o.w = g[d0+3] * (v[3]-mean) * r + bb[d0+3];
    *(float4*)(dst + base) = o;
}

// ---------------- mma helper (raw fp32 bits -> tf32 truncation) ----------------
__device__ __forceinline__ void mma1688(float* c, const uint32_t* a, const uint32_t* b) {
    asm volatile(
        "mma.sync.aligned.m16n8k8.row.col.f32.tf32.tf32.f32 "
        "{%0,%1,%2,%3}, {%4,%5,%6,%7}, {%8,%9}, {%0,%1,%2,%3};"
        : "+f"(c[0]), "+f"(c[1]), "+f"(c[2]), "+f"(c[3])
        : "r"(a[0]), "r"(a[1]), "r"(a[2]), "r"(a[3]),
          "r"(b[0]), "r"(b[1]));
}

// cp.async 16B with zero-fill predication
__device__ __forceinline__ void cp16(float* dst, const float* src, bool pred) {
    uint32_t d = (uint32_t)__cvta_generic_to_shared(dst);
    int sz = pred ? 16 : 0;
    asm volatile("cp.async.cg.shared.global [%0], [%1], 16, %2;"
                 :: "r"(d), "l"(src), "r"(sz));
}
__device__ __forceinline__ void cp_commit() {
    asm volatile("cp.async.commit_group;");
}
template<int N>
__device__ __forceinline__ void cp_wait() {
    asm volatile("cp.async.wait_group %0;" :: "n"(N));
}

// ---------------- tf32 GEMM core: cp.async 3-stage pipeline ----------------
// 64x128 block tile, 128 threads (4 warps along N, warp tile 64x32), BK=16.
// As: [stage][64][ASTR] row-major (m,k); Bs: [stage][16][BSTR] (k,n).
#define BK   16
#define ASTR 20
#define BSTR 136
#define NSTG 3
__device__ __forceinline__ void gemm_core(
    const float* __restrict__ A, const float* __restrict__ W,
    const float* __restrict__ bias, float* __restrict__ C,
    int M, int N, int K, int do_relu, int row0, int col0) {
    __shared__ float As[NSTG][64][ASTR];
    __shared__ float Bs[NSTG][BK][BSTR];
    const int tid = threadIdx.x;
    const int wid = tid >> 5, lane = tid & 31;
    const int wn  = wid * 32;

    const int a_row = tid >> 1, a_k = (tid & 1) * 8;
    const int b_k   = tid >> 5, b_n = (tid & 31) * 4;
    const int a_grow = row0 + a_row;
    const bool a_ok = (a_grow < M);
    const float* a_src = A + (size_t)a_grow * K + a_k;
    const float* b_src = W + (size_t)b_k * N + col0 + b_n;

    auto load_stage = [&](int st, int k0) {
        cp16(&As[st][a_row][a_k],     a_src + k0,     a_ok);
        cp16(&As[st][a_row][a_k + 4], a_src + k0 + 4, a_ok);
        #pragma unroll
        for (int j = 0; j < 4; j++)
            cp16(&Bs[st][b_k + 4*j][b_n], b_src + (size_t)(k0 + 4*j) * N, true);
    };

    float acc[4][4][4];
    #pragma unroll
    for (int mt = 0; mt < 4; mt++)
        #pragma unroll
        for (int nt = 0; nt < 4; nt++)
            #pragma unroll
            for (int i = 0; i < 4; i++) acc[mt][nt][i] = 0.0f;

    // prologue: fill NSTG-1 stages
    #pragma unroll
    for (int s = 0; s < NSTG - 1; s++) {
        load_stage(s, s * BK);
        cp_commit();
    }

    const int r = lane >> 2, c = lane & 3;
    int stage = 0;
    for (int k0 = 0; k0 < K; k0 += BK) {
        cp_wait<NSTG - 2>();
        __syncthreads();
        // prefetch chunk k0 + (NSTG-1)*BK into the stage freed last iteration
        int kn = k0 + (NSTG - 1) * BK;
        if (kn < K) load_stage((stage + NSTG - 1) % NSTG, kn);
        cp_commit();
        // compute on 'stage'
        #pragma unroll
        for (int ks = 0; ks < BK; ks += 8) {
            uint32_t af[4][4], bfr[4][2];
            #pragma unroll
            for (int mt = 0; mt < 4; mt++) {
                int mb = mt * 16 + r;
                af[mt][0] = __float_as_uint(As[stage][mb    ][ks + c    ]);
                af[mt][1] = __float_as_uint(As[stage][mb + 8][ks + c    ]);
                af[mt][2] = __float_as_uint(As[stage][mb    ][ks + c + 4]);
                af[mt][3] = __float_as_uint(As[stage][mb + 8][ks + c + 4]);
            }
            #pragma unroll
            for (int nt = 0; nt < 4; nt++) {
                int nb = wn + nt * 8 + r;
                bfr[nt][0] = __float_as_uint(Bs[stage][ks + c    ][nb]);
                bfr[nt][1] = __float_as_uint(Bs[stage][ks + c + 4][nb]);
            }
            #pragma unroll
            for (int mt = 0; mt < 4; mt++)
                #pragma unroll
                for (int nt = 0; nt < 4; nt++)
                    mma1688(acc[mt][nt], af[mt], bfr[nt]);
        }
        __syncthreads();
        stage = (stage + 1) % NSTG;
    }

    #pragma unroll
    for (int mt = 0; mt < 4; mt++) {
        int rrow = row0 + mt * 16 + (lane >> 2);
        #pragma unroll
        for (int nt = 0; nt < 4; nt++) {
            int ccol = col0 + wn + nt * 8 + (lane & 3) * 2;
            float2 v0 = make_float2(acc[mt][nt][0], acc[mt][nt][1]);
            float2 v1 = make_float2(acc[mt][nt][2], acc[mt][nt][3]);
            if (bias) {
                float b0 = bias[ccol], b1 = bias[ccol + 1];
                v0.x += b0; v0.y += b1;
                v1.x += b0; v1.y += b1;
            }
            if (do_relu) {
                v0.x = fmaxf(v0.x, 0.f); v0.y = fmaxf(v0.y, 0.f);
                v1.x = fmaxf(v1.x, 0.f); v1.y = fmaxf(v1.y, 0.f);
            }
            if (rrow < M)     *(float2*)(C + (size_t)rrow     * N + ccol) = v0;
            if (rrow + 8 < M) *(float2*)(C + (size_t)(rrow+8) * N + ccol) = v1;
        }
    }
}

__global__ __launch_bounds__(128, 4) void mma_gemm_kernel(
    const float* __restrict__ A, const float* __restrict__ W,
    const float* __restrict__ bias, float* __restrict__ C,
    int M, int N, int K, int do_relu) {
    gemm_core(A, W, bias, C, M, N, K, do_relu, blockIdx.y * 64, blockIdx.x * 128);
}

__global__ __launch_bounds__(128, 4) void qkv_gemm_kernel(
    const float* __restrict__ X,
    const float* __restrict__ Wq, const float* __restrict__ Wk,
    const float* __restrict__ Wv,
    float* __restrict__ Qo, float* __restrict__ Ko, float* __restrict__ Vo,
    int M) {
    const float* W = (blockIdx.z == 0) ? Wq : ((blockIdx.z == 1) ? Wk : Wv);
    float*       C = (blockIdx.z == 0) ? Qo : ((blockIdx.z == 1) ? Ko : Vo);
    gemm_core(X, W, nullptr, C, M, DM, DM, 0, blockIdx.y * 64, blockIdx.x * 128);
}

// ---------------- MMA attention (flash-style, tf32 truncation) ----------------
#define SKT 76
#define SVT 72
#define SPT 76
#define ATTN_SMEM_FLOATS (64*SKT + 64*SVT + 64*SVT + 4*16*SPT + 64)

__global__ __launch_bounds__(128) void attn_mma_kernel(
    const float* __restrict__ Q, const float* __restrict__ K,
    const float* __restrict__ V, float* __restrict__ O, int L) {
    extern __shared__ float sm[];
    float* sK  = sm;                       // [64][SKT]
    float* sV  = sK + 64 * SKT;            // [64][SVT]
    float* sQT = sV + 64 * SVT;            // [64][SVT]  (dim-major)
    float* sPa = sQT + 64 * SVT;           // [4][16][SPT]
    float* sW  = sPa + 4 * 16 * SPT;       // [4][16]

    int b = blockIdx.x, h = blockIdx.y, qt = blockIdx.z;
    int tid = threadIdx.x, w = tid >> 5, lane = tid & 31;
    int r = lane >> 2, c = lane & 3;
    int sl = g_seq_len[b];
    size_t base = ((size_t)b * L) * DM + h * DKH;
    int q0 = qt * 64;
    int qb = w * 16;
    float* sP = sPa + w * 16 * SPT;
    float* sWw = sW + w * 16;

    // stage Q^T once
    for (int idx = tid; idx < 64 * 16; idx += 128) {
        int qq = idx >> 4, dd = (idx & 15) * 4;
        int gq = q0 + qq; if (gq >= L) gq = L - 1;
        float4 qv = *(const float4*)(Q + base + (size_t)gq * DM + dd);
        sQT[(dd+0) * SVT + qq] = qv.x;
        sQT[(dd+1) * SVT + qq] = qv.y;
        sQT[(dd+2) * SVT + qq] = qv.z;
        sQT[(dd+3) * SVT + qq] = qv.w;
    }

    float oacc[8][4];
    #pragma unroll
    for (int d = 0; d < 8; d++)
        #pragma unroll
        for (int i = 0; i < 4; i++) oacc[d][i] = 0.0f;
    float mrow[2][2] = {{-3.0e38f, -3.0e38f}, {-3.0e38f, -3.0e38f}};
    float lrow[2][2] = {{0.f, 0.f}, {0.f, 0.f}};

    for (int j0 = 0; j0 < L; j0 += 64) {
        __syncthreads();
        for (int idx = tid; idx < 64 * 16; idx += 128) {
            int kr = idx >> 4, dd = (idx & 15) * 4;
            int gj = j0 + kr;
            float4 kv = make_float4(0.f,0.f,0.f,0.f), vv = kv;
            if (gj < L) {
                kv = *(const float4*)(K + base + (size_t)gj * DM + dd);
                vv = *(const float4*)(V + base + (size_t)gj * DM + dd);
            }
            *(float4*)&sK[kr * SKT + dd] = kv;
            *(float4*)&sV[kr * SVT + dd] = vv;
        }
        __syncthreads();

        float sfr[4][2][4];
        #pragma unroll
        for (int mt = 0; mt < 4; mt++)
            #pragma unroll
            for (int nt = 0; nt < 2; nt++)
                #pragma unroll
                for (int i = 0; i < 4; i++) sfr[mt][nt][i] = 0.f;

        #pragma unroll
        for (int kk = 0; kk < 64; kk += 8) {
            uint32_t bq[2][2];
            #pragma unroll
            for (int nt = 0; nt < 2; nt++) {
                int qn = qb + nt * 8 + r;
                bq[nt][0] = __float_as_uint(sQT[(kk + c    ) * SVT + qn]);
                bq[nt][1] = __float_as_uint(sQT[(kk + c + 4) * SVT + qn]);
            }
            #pragma unroll
            for (int mt = 0; mt < 4; mt++) {
                int mb = mt * 16;
                uint32_t a[4];
                a[0] = __float_as_uint(sK[(mb + r    ) * SKT + kk + c    ]);
                a[1] = __float_as_uint(sK[(mb + r + 8) * SKT + kk + c    ]);
                a[2] = __float_as_uint(sK[(mb + r    ) * SKT + kk + c + 4]);
                a[3] = __float_as_uint(sK[(mb + r + 8) * SKT + kk + c + 4]);
                #pragma unroll
                for (int nt = 0; nt < 2; nt++)
                    mma1688(sfr[mt][nt], a, bq[nt]);
            }
        }

        float scl[2][2];
        #pragma unroll
        for (int nt = 0; nt < 2; nt++) {
            #pragma unroll
            for (int i = 0; i < 2; i++) {
                float cm = -3.0e38f;
                #pragma unroll
                for (int mt = 0; mt < 4; mt++) {
                    int j = j0 + mt * 16 + r;
                    float s0 = (j     < sl) ? sfr[mt][nt][i]   * 0.125f : -1e9f;
                    float s1 = (j + 8 < sl) ? sfr[mt][nt][2+i] * 0.125f : -1e9f;
                    sfr[mt][nt][i]   = s0;
                    sfr[mt][nt][2+i] = s1;
                    cm = fmaxf(cm, fmaxf(s0, s1));
                }
                cm = fmaxf(cm, __shfl_xor_sync(0xFFFFFFFFu, cm, 4));
                cm = fmaxf(cm, __shfl_xor_sync(0xFFFFFFFFu, cm, 8));
                cm = fmaxf(cm, __shfl_xor_sync(0xFFFFFFFFu, cm, 16));
                float mnew = fmaxf(mrow[nt][i], cm);
                float sc = expf(mrow[nt][i] - mnew);
                mrow[nt][i] = mnew;
                scl[nt][i] = sc;
                float ls = 0.f;
                #pragma unroll
                for (int mt = 0; mt < 4; mt++) {
                    float p0 = expf(sfr[mt][nt][i]   - mnew);
                    float p1 = expf(sfr[mt][nt][2+i] - mnew);
                    sfr[mt][nt][i]   = p0;
                    sfr[mt][nt][2+i] = p1;
                    ls += p0 + p1;
                }
                ls += __shfl_xor_sync(0xFFFFFFFFu, ls, 4);
                ls += __shfl_xor_sync(0xFFFFFFFFu, ls, 8);
                ls += __shfl_xor_sync(0xFFFFFFFFu, ls, 16);
                lrow[nt][i] = lrow[nt][i] * sc + ls;
            }
        }
        if (r == 0) {
            #pragma unroll
            for (int nt = 0; nt < 2; nt++)
                #pragma unroll
                for (int i = 0; i < 2; i++)
                    sWw[nt * 8 + 2 * c + i] = scl[nt][i];
        }
        __syncwarp();
        float rs0 = sWw[r], rs1 = sWw[r + 8];
        #pragma unroll
        for (int d = 0; d < 8; d++) {
            oacc[d][0] *= rs0; oacc[d][1] *= rs0;
            oacc[d][2] *= rs1; oacc[d][3] *= rs1;
        }
        #pragma unroll
        for (int nt = 0; nt < 2; nt++)
            #pragma unroll
            for (int i = 0; i < 2; i++) {
                int qq = nt * 8 + 2 * c + i;
                #pragma unroll
                for (int mt = 0; mt < 4; mt++) {
                    sP[qq * SPT + mt * 16 + r    ] = sfr[mt][nt][i];
                    sP[qq * SPT + mt * 16 + r + 8] = sfr[mt][nt][2+i];
                }
            }
        __syncwarp();
        #pragma unroll
        for (int kk = 0; kk < 64; kk += 8) {
            uint32_t a[4];
            a[0] = __float_as_uint(sP[(r    ) * SPT + kk + c    ]);
            a[1] = __float_as_uint(sP[(r + 8) * SPT + kk + c    ]);
            a[2] = __float_as_uint(sP[(r    ) * SPT + kk + c + 4]);
            a[3] = __float_as_uint(sP[(r + 8) * SPT + kk + c + 4]);
            #pragma unroll
            for (int dn = 0; dn < 8; dn++) {
                uint32_t bb2[2];
                bb2[0] = __float_as_uint(sV[(kk + c    ) * SVT + dn * 8 + r]);
                bb2[1] = __float_as_uint(sV[(kk + c + 4) * SVT + dn * 8 + r]);
                mma1688(oacc[dn], a, bb2);
            }
        }
    }

    if (r == 0) {
        #pragma unroll
        for (int nt = 0; nt < 2; nt++)
            #pragma unroll
            for (int i = 0; i < 2; i++)
                sWw[nt * 8 + 2 * c + i] = 1.0f / lrow[nt][i];
    }
    __syncwarp();
    float inv0 = sWw[r], inv1 = sWw[r + 8];
    int gq0 = q0 + qb + r, gq1 = gq0 + 8;
    #pragma unroll
    for (int dn = 0; dn < 8; dn++) {
        int col = dn * 8 + 2 * c;
        if (gq0 < L)
            *(float2*)(O + base + (size_t)gq0 * DM + col) =
                make_float2(oacc[dn][0] * inv0, oacc[dn][1] * inv0);
        if (gq1 < L)
            *(float2*)(O + base + (size_t)gq1 * DM + col) =
                make_float2(oacc[dn][2] * inv1, oacc[dn][3] * inv1);
    }
}

// ---------------- mask writeout ----------------
__global__ void mask_kernel(float* __restrict__ out, int L) {
    int idx = blockIdx.x * blockDim.x + threadIdx.x;
    if (idx < BB * L) {
        int b = idx / L, l = idx - b * L;
        out[(size_t)BB * L * DM + idx] = (l < g_seq_len[b]) ? 1.0f : 0.0f;
    }
}

// ---------------- host launcher ----------------
extern "C" void kernel_launch(void* const* d_in, const int* in_sizes, int n_in,
                              void* d_out, int out_size) {
    const int*   poi_type = (const int*)  d_in[0];
    const float* loc_emb  = (const float*)d_in[1];
    const int*   npl      = (const int*)  d_in[2];
    const int*   ttn      = (const int*)  d_in[3];
    const float* emb      = (const float*)d_in[4];
    const float* Wq       = (const float*)d_in[5];
    const float* Wk       = (const float*)d_in[6];
    const float* Wv       = (const float*)d_in[7];
    const float* Wo       = (const float*)d_in[8];
    const float* bo       = (const float*)d_in[9];
    const float* ln1_g    = (const float*)d_in[10];
    const float* ln1_b    = (const float*)d_in[11];
    const float* W1       = (const float*)d_in[12];
    const float* b1       = (const float*)d_in[13];
    const float* W2       = (const float*)d_in[14];
    const float* b2       = (const float*)d_in[15];
    const float* ln2_g    = (const float*)d_in[16];
    const float* ln2_b    = (const float*)d_in[17];
    const float* lnf_g    = (const float*)d_in[18];
    const float* lnf_b    = (const float*)d_in[19];

    int L, with_mask;
    if (out_size % (BB * (DM + 1)) == 0) { L = out_size / (BB * (DM + 1)); with_mask = 1; }
    else                                 { L = out_size / (BB * DM);        with_mask = 0; }
    const int M = BB * L;

    float *x, *q, *k, *v, *ao, *y, *hbuf;
    cudaGetSymbolAddress((void**)&x,    g_x);
    cudaGetSymbolAddress((void**)&q,    g_q);
    cudaGetSymbolAddress((void**)&k,    g_k);
    cudaGetSymbolAddress((void**)&v,    g_v);
    cudaGetSymbolAddress((void**)&ao,   g_ao);
    cudaGetSymbolAddress((void**)&y,    g_y);
    cudaGetSymbolAddress((void**)&hbuf, g_h);

    int attn_smem = ATTN_SMEM_FLOATS * 4;
    cudaFuncSetAttribute(attn_mma_kernel,
                         cudaFuncAttributeMaxDynamicSharedMemorySize,
                         attn_smem);

    pack_kernel<<<1, 64>>>(npl, ttn, L);
    embed_ln_kernel<<<M, 128>>>(poi_type, loc_emb, emb, lnf_g, lnf_b, L);

    int my = (M + 63) / 64;
    int nq = (L + 63) / 64;
    dim3 g512(4, my);
    dim3 g2048(16, my);
    dim3 gqkv(4, my, 3);
    dim3 gattn(BB, NH, nq);

    for (int l = 0; l < NLAY; l++) {
        const float* wq = Wq + (size_t)l * DM * DM;
        const float* wk = Wk + (size_t)l * DM * DM;
        const float* wv = Wv + (size_t)l * DM * DM;
        const float* wo = Wo + (size_t)l * DM * DM;
        const float* w1 = W1 + (size_t)l * DM * DI;
        const float* w2 = W2 + (size_t)l * DI * DM;

        qkv_gemm_kernel<<<gqkv, 128>>>(x, wq, wk, wv, q, k, v, M);
        attn_mma_kernel<<<gattn, 128, attn_smem>>>(q, k, v, ao, L);
        mma_gemm_kernel<<<g512, 128>>>(ao, wo, bo + (size_t)l * DM, y, M, DM, DM, 0);
        resid_ln_kernel<<<M, 128>>>(x, y, ln1_g + (size_t)l * DM, ln1_b + (size_t)l * DM, x);
        mma_gemm_kernel<<<g2048, 128>>>(x, w1, b1 + (size_t)l * DI, hbuf, M, DI, DM, 1);
        mma_gemm_kernel<<<g512, 128>>>(hbuf, w2, b2 + (size_t)l * DM, y, M, DM, DI, 0);
        float* dst = (l == NLAY - 1) ? (float*)d_out : x;
        resid_ln_kernel<<<M, 128>>>(x, y, ln2_g + (size_t)l * DM, ln2_b + (size_t)l * DM, dst);
    }

    if (with_mask)
        mask_kernel<<<(BB * L + 255) / 256, 256>>>((float*)d_out, L);
}